// round 14
// baseline (speedup 1.0000x reference)
#include <cuda_runtime.h>
#include <cuda_bf16.h>
#include <cuda_fp16.h>

#define SEQ   1024
#define DIM   64
#define BH    64
#define NB    32768
#define INV_N (1.0f/1048576.0f)
#define STRD  72          // smem row stride in 16-bit units (144B) -> conflict-free ldmatrix

// plane stride (words / uint4) for plane-major replica counters
#define PLW   ((size_t)BH*NB)        // 2,097,152 words  (8MB per plane)
#define PL4   (PLW/4)                // 524,288 uint4

// ---------------- scratch ----------------
__device__ __nv_bfloat16 g_qhi[(size_t)BH*SEQ*DIM];
__device__ __nv_bfloat16 g_qlo[(size_t)BH*SEQ*DIM];
__device__ __nv_bfloat16 g_khi[(size_t)BH*SEQ*DIM];
__device__ __nv_bfloat16 g_klo[(size_t)BH*SEQ*DIM];
__device__ unsigned short g_vt16[(size_t)BH*DIM*SEQ];  // V^T fp16 [head][d][k] (8MB)
__device__ unsigned short g_bins[(size_t)BH*SEQ*SEQ];  // u16 bin per score (128MB)
__device__ unsigned      g_hist2[(size_t)4*BH*NB];     // PLANE-MAJOR: [rep][head][bin] (32MB)
__device__ unsigned      g_cnt[(size_t)BH*NB];         // per-bin totals (8MB)
__device__ unsigned short g_wlut[(size_t)BH*NB];       // fp16 weight per bin (4MB)
__device__ unsigned      g_part[BH*32];

// ---------------- helpers ----------------
__device__ __forceinline__ int binof(float x) {
    int b = (int)((x + 1.0f) * 16384.0f);
    b = b < 0 ? 0 : b;
    b = b > (NB-1) ? (NB-1) : b;
    return b;
}
__device__ __forceinline__ unsigned s2u(const void* p) {
    unsigned a;
    asm("{ .reg .u64 t; cvta.to.shared.u64 t, %1; cvt.u32.u64 %0, t; }" : "=r"(a) : "l"(p));
    return a;
}
__device__ __forceinline__ void ldm4(unsigned r[4], unsigned a) {
    asm volatile("ldmatrix.sync.aligned.m8n8.x4.shared.b16 {%0,%1,%2,%3}, [%4];"
        : "=r"(r[0]), "=r"(r[1]), "=r"(r[2]), "=r"(r[3]) : "r"(a));
}
__device__ __forceinline__ void mma_bf16(float c[4], const unsigned a[4],
                                         unsigned b0, unsigned b1) {
    asm volatile("mma.sync.aligned.m16n8k16.row.col.f32.bf16.bf16.f32 "
        "{%0,%1,%2,%3}, {%4,%5,%6,%7}, {%8,%9}, {%0,%1,%2,%3};"
        : "+f"(c[0]), "+f"(c[1]), "+f"(c[2]), "+f"(c[3])
        : "r"(a[0]), "r"(a[1]), "r"(a[2]), "r"(a[3]), "r"(b0), "r"(b1));
}
__device__ __forceinline__ void mma_f16(float c[4], const unsigned a[4],
                                        unsigned b0, unsigned b1) {
    asm volatile("mma.sync.aligned.m16n8k16.row.col.f32.f16.f16.f32 "
        "{%0,%1,%2,%3}, {%4,%5,%6,%7}, {%8,%9}, {%0,%1,%2,%3};"
        : "+f"(c[0]), "+f"(c[1]), "+f"(c[2]), "+f"(c[3])
        : "r"(a[0]), "r"(a[1]), "r"(a[2]), "r"(a[3]), "r"(b0), "r"(b1));
}
__device__ __forceinline__ void split2(float x, __nv_bfloat16& h, __nv_bfloat16& l) {
    h = __float2bfloat16_rn(x);
    l = __float2bfloat16_rn(x - __bfloat162float(h));
}

// ---------------- normalize + split Q,K to bf16 hi/lo ----------------
__global__ __launch_bounds__(256) void k_qksplit(const float* __restrict__ q,
                                                 const float* __restrict__ k) {
    int w    = blockIdx.x * 8 + (threadIdx.x >> 5);
    int lane = threadIdx.x & 31;
    int r    = w & 65535;
    const float* src = (w < 65536) ? q + (size_t)r*64 : k + (size_t)r*64;
    __nv_bfloat16* dh = (w < 65536) ? g_qhi : g_khi;
    __nv_bfloat16* dl = (w < 65536) ? g_qlo : g_klo;
    float x0 = src[lane], x1 = src[lane+32];
    float ss = x0*x0 + x1*x1;
    #pragma unroll
    for (int o = 16; o; o >>= 1) ss += __shfl_xor_sync(0xffffffffu, ss, o);
    float inv = 1.0f / (sqrtf(ss) + 1e-5f);
    x0 *= inv; x1 *= inv;
    __nv_bfloat16 h, l;
    split2(x0, h, l); dh[(size_t)r*64 + lane]      = h; dl[(size_t)r*64 + lane]      = l;
    split2(x1, h, l); dh[(size_t)r*64 + lane + 32] = h; dl[(size_t)r*64 + lane + 32] = l;
}

// ---------------- transpose V -> fp16 V^T ----------------
__global__ __launch_bounds__(256) void k_vsplit(const float* __restrict__ V) {
    __shared__ float t[64][65];
    int head = blockIdx.y, kc = blockIdx.x, tid = threadIdx.x;
    const float* src = V + ((size_t)head*SEQ + kc*64) * 64;
    #pragma unroll
    for (int i = 0; i < 4; i++) {
        int idx = tid + i*256;
        int r = idx >> 4, c4 = idx & 15;
        float4 v = ((const float4*)(src + (size_t)r*64))[c4];
        t[r][c4*4+0]=v.x; t[r][c4*4+1]=v.y; t[r][c4*4+2]=v.z; t[r][c4*4+3]=v.w;
    }
    __syncthreads();
    #pragma unroll
    for (int i = 0; i < 8; i++) {
        int idx = tid + i*256;
        int d = idx >> 5, rp = idx & 31;
        unsigned short h0 = __half_as_ushort(__float2half_rn(t[rp*2][d]));
        unsigned short h1 = __half_as_ushort(__float2half_rn(t[rp*2+1][d]));
        size_t o = ((size_t)head*64 + d)*SEQ + kc*64 + rp*2;
        *(unsigned*)(g_vt16 + o) = (unsigned)h0 | ((unsigned)h1 << 16);
    }
}

// -------- score GEMM (HMMA, split bf16) -> u16 bins (streaming stores) -------
__global__ __launch_bounds__(256) void k_score() {
    extern __shared__ __nv_bfloat16 sm[];
    const int TQH = 0, TQL = 128*STRD, TKH = 2*128*STRD, TKL = 3*128*STRD;
    int tid = threadIdx.x, wid = tid >> 5, lane = tid & 31;
    int kt = blockIdx.x, qt = blockIdx.y, head = blockIdx.z;

    size_t bq = ((size_t)head*SEQ + qt*128) * 64;
    size_t bk = ((size_t)head*SEQ + kt*128) * 64;
    const uint4* srcs[4] = { (const uint4*)(g_qhi+bq), (const uint4*)(g_qlo+bq),
                             (const uint4*)(g_khi+bk), (const uint4*)(g_klo+bk) };
    const int bases[4] = { TQH, TQL, TKH, TKL };
    #pragma unroll
    for (int a = 0; a < 4; a++)
        #pragma unroll
        for (int j = 0; j < 4; j++) {
            int idx = tid + j*256;
            int r = idx >> 3, c = idx & 7;
            uint4 v = srcs[a][idx];
            *(uint4*)&sm[bases[a] + r*STRD + c*8] = v;
        }
    __syncthreads();

    unsigned sb = s2u(sm);
    unsigned arow = wid*16 + (lane & 15);
    unsigned acol = (lane >> 4) * 8;
    unsigned aH = sb + (TQH + arow*STRD + acol) * 2;
    unsigned aL = sb + (TQL + arow*STRD + acol) * 2;
    unsigned ah[4][4], al[4][4];
    #pragma unroll
    for (int ks = 0; ks < 4; ks++) { ldm4(ah[ks], aH + ks*32); ldm4(al[ks], aL + ks*32); }

    unsigned brow = (lane & 7) + ((lane >> 4) << 3);
    unsigned bcol = ((lane >> 3) & 1) * 8;
    unsigned bH = sb + (TKH + brow*STRD + bcol) * 2;
    unsigned bL = sb + (TKL + brow*STRD + bcol) * 2;

    float acc[16][4];
    #pragma unroll
    for (int i = 0; i < 16; i++) { acc[i][0]=0; acc[i][1]=0; acc[i][2]=0; acc[i][3]=0; }

    #pragma unroll
    for (int np = 0; np < 8; np++) {
        #pragma unroll
        for (int ks = 0; ks < 4; ks++) {
            unsigned bh[4], bl[4];
            ldm4(bh, bH + np*16*STRD*2 + ks*32);
            ldm4(bl, bL + np*16*STRD*2 + ks*32);
            mma_bf16(acc[2*np],   ah[ks], bh[0], bh[1]);
            mma_bf16(acc[2*np+1], ah[ks], bh[2], bh[3]);
            mma_bf16(acc[2*np],   ah[ks], bl[0], bl[1]);
            mma_bf16(acc[2*np+1], ah[ks], bl[2], bl[3]);
            mma_bf16(acc[2*np],   al[ks], bh[0], bh[1]);
            mma_bf16(acc[2*np+1], al[ks], bh[2], bh[3]);
        }
    }

    int r0 = wid*16 + (lane >> 2);
    int cb = (lane & 3) * 2;
    unsigned short* bp0 = g_bins + ((size_t)head*SEQ + qt*128 + r0) * SEQ + kt*128;
    unsigned short* bp1 = bp0 + 8*SEQ;
    #pragma unroll
    for (int nt = 0; nt < 16; nt++) {
        int c = nt*8 + cb;
        unsigned b0 = binof(acc[nt][0]), b1 = binof(acc[nt][1]);
        unsigned b2 = binof(acc[nt][2]), b3 = binof(acc[nt][3]);
        __stcs((unsigned*)&bp0[c], b0 | (b1 << 16));
        __stcs((unsigned*)&bp1[c], b2 | (b3 << 16));
    }
}

// --- histogram build: plane-major replicas spread hot bins across L2 slices --
__global__ __launch_bounds__(256) void k_hist() {
    int tid = threadIdx.x;
    int lane = tid & 31;
    #pragma unroll
    for (int j = 0; j < 2; j++) {
        unsigned gi = blockIdx.x * 512u + j*256 + tid;       // uint4 index (8 bins)
        uint4 v = __ldcs((const uint4*)g_bins + gi);
        unsigned* h = g_hist2 + (size_t)(gi >> 17) * NB;      // head base in plane 0
        unsigned r0 = (lane + j) & 3;
        atomicAdd(&h[(v.x & 0xffffu) + PLW*r0],           1u);
        atomicAdd(&h[(v.x >> 16)     + PLW*((r0+1)&3)],   1u);
        atomicAdd(&h[(v.y & 0xffffu) + PLW*((r0+2)&3)],   1u);
        atomicAdd(&h[(v.y >> 16)     + PLW*((r0+3)&3)],   1u);
        atomicAdd(&h[(v.z & 0xffffu) + PLW*r0],           1u);
        atomicAdd(&h[(v.z >> 16)     + PLW*((r0+1)&3)],   1u);
        atomicAdd(&h[(v.w & 0xffffu) + PLW*((r0+2)&3)],   1u);
        atomicAdd(&h[(v.w >> 16)     + PLW*((r0+3)&3)],   1u);
    }
}

// ---- reduce 4 planes -> per-bin counts + chunk sums; ZERO planes in place ---
__global__ __launch_bounds__(256) void k_hpart() {
    int head = blockIdx.y, chunk = blockIdx.x, t = threadIdx.x;
    uint4* p = (uint4*)g_hist2 + (size_t)head * (NB/4);      // head base, plane 0
    unsigned* cnt = g_cnt + (size_t)head*NB;
    int g4 = chunk*256 + t;                                  // uint4 group (4 bins)
    uint4 a0 = __ldcs((const uint4*)p + g4);
    uint4 a1 = __ldcs((const uint4*)p + PL4 + g4);
    uint4 a2 = __ldcs((const uint4*)p + 2*PL4 + g4);
    uint4 a3 = __ldcs((const uint4*)p + 3*PL4 + g4);
    uint4 s;
    s.x = a0.x + a1.x + a2.x + a3.x;
    s.y = a0.y + a1.y + a2.y + a3.y;
    s.z = a0.z + a1.z + a2.z + a3.z;
    s.w = a0.w + a1.w + a2.w + a3.w;
    ((uint4*)cnt)[g4] = s;
    uint4 z = make_uint4(0u,0u,0u,0u);
    p[g4] = z; p[PL4 + g4] = z; p[2*PL4 + g4] = z; p[3*PL4 + g4] = z;  // reset
    unsigned tot = s.x + s.y + s.z + s.w;
    __shared__ unsigned sm[8];
    #pragma unroll
    for (int o = 16; o; o >>= 1) tot += __shfl_xor_sync(0xffffffffu, tot, o);
    if ((t & 31) == 0) sm[t >> 5] = tot;
    __syncthreads();
    if (t < 8) {
        unsigned v = sm[t];
        #pragma unroll
        for (int o = 4; o; o >>= 1) v += __shfl_xor_sync(0xffu, v, o);
        if (t == 0) g_part[head*32 + chunk] = v;
    }
}
__global__ __launch_bounds__(32) void k_hscan() {
    int head = blockIdx.x, t = threadIdx.x;
    unsigned v = g_part[head*32 + t];
    unsigned s = v;
    #pragma unroll
    for (int off = 1; off < 32; off <<= 1) {
        unsigned o = __shfl_down_sync(0xffffffffu, s, off);
        if (t + off < 32) s += o;
    }
    g_part[head*32 + t] = s - v;
}
__global__ __launch_bounds__(256) void k_hfinal() {
    int head = blockIdx.y, chunk = blockIdx.x, t = threadIdx.x;
    const unsigned* h = g_cnt + (size_t)head*NB + chunk*1024;
    uint4 v = ((const uint4*)h)[t];
    unsigned tot = v.x + v.y + v.z + v.w;
    __shared__ unsigned s[256];
    s[t] = tot; __syncthreads();
    for (int off = 1; off < 256; off <<= 1) {
        unsigned add = (t + off < 256) ? s[t + off] : 0u;
        __syncthreads();
        s[t] += add;
        __syncthreads();
    }
    unsigned above = s[t] - tot + g_part[head*32 + chunk];
    unsigned SA3 = above;
    unsigned SA2 = SA3 + v.w;
    unsigned SA1 = SA2 + v.z;
    unsigned SA0 = SA1 + v.y;
    float w0 = -__logf(((float)SA0 + 0.5f*((float)v.x - 1.0f) + 1.0f) * INV_N);
    float w1 = -__logf(((float)SA1 + 0.5f*((float)v.y - 1.0f) + 1.0f) * INV_N);
    float w2 = -__logf(((float)SA2 + 0.5f*((float)v.z - 1.0f) + 1.0f) * INV_N);
    float w3 = -__logf(((float)SA3 + 0.5f*((float)v.w - 1.0f) + 1.0f) * INV_N);
    unsigned p0 = (unsigned)__half_as_ushort(__float2half_rn(w0))
                | ((unsigned)__half_as_ushort(__float2half_rn(w1)) << 16);
    unsigned p1 = (unsigned)__half_as_ushort(__float2half_rn(w2))
                | ((unsigned)__half_as_ushort(__float2half_rn(w3)) << 16);
    ((uint2*)(g_wlut + (size_t)head*NB))[chunk*256 + t] = make_uint2(p0, p1);
}

// ---------------- output GEMM: bins -> (smem LUT) -> fp16 W, O=(W@V)/rowsum --
#define OS_LUT 0
#define OS_W   65536
#define OS_V   (65536 + 128*STRD*2)
#define OS_RS  (65536 + 128*STRD*2 + 64*STRD*2)
#define OS_TOT (OS_RS + 512)
__global__ __launch_bounds__(256, 2) void k_out(float* __restrict__ O) {
    extern __shared__ char smc[];
    unsigned short* lut = (unsigned short*)(smc + OS_LUT);
    unsigned short* Ws  = (unsigned short*)(smc + OS_W);
    unsigned short* Vs  = (unsigned short*)(smc + OS_V);
    float* rs           = (float*)(smc + OS_RS);
    int tid = threadIdx.x, wid = tid >> 5, lane = tid & 31;
    int qt = blockIdx.x, head = blockIdx.y;

    {
        const uint4* src = (const uint4*)(g_wlut + (size_t)head*NB);
        uint4* dst = (uint4*)lut;
        #pragma unroll
        for (int j = 0; j < 16; j++) dst[tid + j*256] = src[tid + j*256];
    }
    __syncthreads();

    size_t wbase = (size_t)head*SEQ + qt*128;
    size_t vbase = (size_t)head*64;

    unsigned sb = s2u(smc);
    unsigned arow = wid*16 + (lane & 15);
    unsigned acol = (lane >> 4) * 8;
    unsigned aA = sb + OS_W + (arow*STRD + acol) * 2;
    unsigned brow = (lane & 7) + ((lane >> 4) << 3);
    unsigned bcol = ((lane >> 3) & 1) * 8;
    unsigned bB = sb + OS_V + (brow*STRD + bcol) * 2;

    float acc[8][4];
    #pragma unroll
    for (int i = 0; i < 8; i++) { acc[i][0]=0; acc[i][1]=0; acc[i][2]=0; acc[i][3]=0; }
    float psum[4] = {0.f, 0.f, 0.f, 0.f};

    for (int ch = 0; ch < 16; ch++) {
        #pragma unroll
        for (int j = 0; j < 4; j++) {
            int idx = tid + j*256;
            int r = idx >> 3, c = idx & 7;
            uint4 b = __ldcs((const uint4*)(g_bins + (wbase + r)*SEQ + ch*64 + c*8));
            unsigned short w0 = lut[b.x & 0xffffu], w1 = lut[b.x >> 16];
            unsigned short w2 = lut[b.y & 0xffffu], w3 = lut[b.y >> 16];
            unsigned short w4 = lut[b.z & 0xffffu], w5 = lut[b.z >> 16];
            unsigned short w6 = lut[b.w & 0xffffu], w7 = lut[b.w >> 16];
            uint4 wv;
            wv.x = (unsigned)w0 | ((unsigned)w1 << 16);
            wv.y = (unsigned)w2 | ((unsigned)w3 << 16);
            wv.z = (unsigned)w4 | ((unsigned)w5 << 16);
            wv.w = (unsigned)w6 | ((unsigned)w7 << 16);
            *(uint4*)&Ws[r*STRD + c*8] = wv;
            psum[j] += __half2float(__ushort_as_half(w0)) + __half2float(__ushort_as_half(w1))
                     + __half2float(__ushort_as_half(w2)) + __half2float(__ushort_as_half(w3))
                     + __half2float(__ushort_as_half(w4)) + __half2float(__ushort_as_half(w5))
                     + __half2float(__ushort_as_half(w6)) + __half2float(__ushort_as_half(w7));
        }
        #pragma unroll
        for (int j = 0; j < 2; j++) {
            int idx = tid + j*256;
            int r = idx >> 3, c = idx & 7;
            *(uint4*)&Vs[r*STRD + c*8] =
                *(const uint4*)(g_vt16 + (vbase + r)*SEQ + ch*64 + c*8);
        }
        __syncthreads();

        unsigned af[4][4];
        #pragma unroll
        for (int ks = 0; ks < 4; ks++) ldm4(af[ks], aA + ks*32);
        #pragma unroll
        for (int np = 0; np < 4; np++) {
            #pragma unroll
            for (int ks = 0; ks < 4; ks++) {
                unsigned bf[4];
                ldm4(bf, bB + np*16*STRD*2 + ks*32);
                mma_f16(acc[2*np],   af[ks], bf[0], bf[1]);
                mma_f16(acc[2*np+1], af[ks], bf[2], bf[3]);
            }
        }
        __syncthreads();
    }

    #pragma unroll
    for (int j = 0; j < 4; j++) {
        float v = psum[j];
        v += __shfl_down_sync(0xffffffffu, v, 4);
        v += __shfl_down_sync(0xffffffffu, v, 2);
        v += __shfl_down_sync(0xffffffffu, v, 1);
        if ((tid & 7) == 0) rs[(tid >> 3) + 32*j] = v;
    }
    __syncthreads();

    int r0 = wid*16 + (lane >> 2);
    int cb = (lane & 3) * 2;
    float inv0 = 1.0f / rs[r0];
    float inv1 = 1.0f / rs[r0 + 8];
    float* op0 = O + ((size_t)head*SEQ + qt*128 + r0) * 64;
    float* op1 = op0 + 8*64;
    #pragma unroll
    for (int nt = 0; nt < 8; nt++) {
        int c = nt*8 + cb;
        *(float2*)&op0[c] = make_float2(acc[nt][0]*inv0, acc[nt][1]*inv0);
        *(float2*)&op1[c] = make_float2(acc[nt][2]*inv1, acc[nt][3]*inv1);
    }
}

// ---------------- launch (single stream, serial — measured fastest) ---------
extern "C" void kernel_launch(void* const* d_in, const int* in_sizes, int n_in,
                              void* d_out, int out_size) {
    const float* q = (const float*)d_in[0];
    const float* k = (const float*)d_in[1];
    const float* v = (const float*)d_in[2];
    float* o = (float*)d_out;

    cudaFuncSetAttribute(k_score, cudaFuncAttributeMaxDynamicSharedMemorySize, 4*128*STRD*2);
    cudaFuncSetAttribute(k_out,   cudaFuncAttributeMaxDynamicSharedMemorySize, OS_TOT);

    k_qksplit<<<16384, 256>>>(q, k);
    k_vsplit <<<dim3(16,64), 256>>>(v);
    k_score  <<<dim3(8,8,64), 256, 4*128*STRD*2>>>();
    k_hist   <<<16384, 256>>>();
    k_hpart  <<<dim3(32,64), 256>>>();
    k_hscan  <<<64, 32>>>();
    k_hfinal <<<dim3(32,64), 256>>>();
    k_out    <<<dim3(8,64), 256, OS_TOT>>>(o);
}

// round 15
// speedup vs baseline: 1.1346x; 1.1346x over previous
#include <cuda_runtime.h>
#include <cuda_bf16.h>
#include <cuda_fp16.h>

#define SEQ   1024
#define DIM   64
#define BH    64
#define NB    16384
#define INV_N (1.0f/1048576.0f)
#define STRD  72          // smem row stride in 16-bit units (144B) -> conflict-free ldmatrix

// ---------------- scratch ----------------
__device__ __nv_bfloat16 g_qhi[(size_t)BH*SEQ*DIM];
__device__ __nv_bfloat16 g_qlo[(size_t)BH*SEQ*DIM];
__device__ __nv_bfloat16 g_khi[(size_t)BH*SEQ*DIM];
__device__ __nv_bfloat16 g_klo[(size_t)BH*SEQ*DIM];
__device__ unsigned short g_vt16[(size_t)BH*DIM*SEQ];  // V^T fp16 [head][d][k] (8MB)
__device__ unsigned short g_bins[(size_t)BH*SEQ*SEQ];  // u16 bin per score (128MB)
__device__ unsigned      g_hist2[(size_t)BH*NB*8];     // 8 u32 interleaved replicas/bin (32MB)
__device__ unsigned      g_cnt[(size_t)BH*NB];         // per-bin totals (4MB)
__device__ unsigned short g_wlut[(size_t)BH*NB];       // fp16 weight per bin (2MB)
__device__ unsigned      g_part[BH*16];

// ---------------- helpers ----------------
__device__ __forceinline__ int binof(float x) {
    int b = (int)((x + 1.0f) * 8192.0f);
    b = b < 0 ? 0 : b;
    b = b > (NB-1) ? (NB-1) : b;
    return b;
}
__device__ __forceinline__ unsigned s2u(const void* p) {
    unsigned a;
    asm("{ .reg .u64 t; cvta.to.shared.u64 t, %1; cvt.u32.u64 %0, t; }" : "=r"(a) : "l"(p));
    return a;
}
__device__ __forceinline__ void ldm4(unsigned r[4], unsigned a) {
    asm volatile("ldmatrix.sync.aligned.m8n8.x4.shared.b16 {%0,%1,%2,%3}, [%4];"
        : "=r"(r[0]), "=r"(r[1]), "=r"(r[2]), "=r"(r[3]) : "r"(a));
}
__device__ __forceinline__ void mma_bf16(float c[4], const unsigned a[4],
                                         unsigned b0, unsigned b1) {
    asm volatile("mma.sync.aligned.m16n8k16.row.col.f32.bf16.bf16.f32 "
        "{%0,%1,%2,%3}, {%4,%5,%6,%7}, {%8,%9}, {%0,%1,%2,%3};"
        : "+f"(c[0]), "+f"(c[1]), "+f"(c[2]), "+f"(c[3])
        : "r"(a[0]), "r"(a[1]), "r"(a[2]), "r"(a[3]), "r"(b0), "r"(b1));
}
__device__ __forceinline__ void mma_f16(float c[4], const unsigned a[4],
                                        unsigned b0, unsigned b1) {
    asm volatile("mma.sync.aligned.m16n8k16.row.col.f32.f16.f16.f32 "
        "{%0,%1,%2,%3}, {%4,%5,%6,%7}, {%8,%9}, {%0,%1,%2,%3};"
        : "+f"(c[0]), "+f"(c[1]), "+f"(c[2]), "+f"(c[3])
        : "r"(a[0]), "r"(a[1]), "r"(a[2]), "r"(a[3]), "r"(b0), "r"(b1));
}
__device__ __forceinline__ void split2(float x, __nv_bfloat16& h, __nv_bfloat16& l) {
    h = __float2bfloat16_rn(x);
    l = __float2bfloat16_rn(x - __bfloat162float(h));
}

// ---------------- normalize + split Q,K to bf16 hi/lo ----------------
__global__ __launch_bounds__(256) void k_qksplit(const float* __restrict__ q,
                                                 const float* __restrict__ k) {
    int w    = blockIdx.x * 8 + (threadIdx.x >> 5);
    int lane = threadIdx.x & 31;
    int r    = w & 65535;
    const float* src = (w < 65536) ? q + (size_t)r*64 : k + (size_t)r*64;
    __nv_bfloat16* dh = (w < 65536) ? g_qhi : g_khi;
    __nv_bfloat16* dl = (w < 65536) ? g_qlo : g_klo;
    float x0 = src[lane], x1 = src[lane+32];
    float ss = x0*x0 + x1*x1;
    #pragma unroll
    for (int o = 16; o; o >>= 1) ss += __shfl_xor_sync(0xffffffffu, ss, o);
    float inv = 1.0f / (sqrtf(ss) + 1e-5f);
    x0 *= inv; x1 *= inv;
    __nv_bfloat16 h, l;
    split2(x0, h, l); dh[(size_t)r*64 + lane]      = h; dl[(size_t)r*64 + lane]      = l;
    split2(x1, h, l); dh[(size_t)r*64 + lane + 32] = h; dl[(size_t)r*64 + lane + 32] = l;
}

// ---------------- transpose V -> fp16 V^T ----------------
__global__ __launch_bounds__(256) void k_vsplit(const float* __restrict__ V) {
    __shared__ float t[64][65];
    int head = blockIdx.y, kc = blockIdx.x, tid = threadIdx.x;
    const float* src = V + ((size_t)head*SEQ + kc*64) * 64;
    #pragma unroll
    for (int i = 0; i < 4; i++) {
        int idx = tid + i*256;
        int r = idx >> 4, c4 = idx & 15;
        float4 v = ((const float4*)(src + (size_t)r*64))[c4];
        t[r][c4*4+0]=v.x; t[r][c4*4+1]=v.y; t[r][c4*4+2]=v.z; t[r][c4*4+3]=v.w;
    }
    __syncthreads();
    #pragma unroll
    for (int i = 0; i < 8; i++) {
        int idx = tid + i*256;
        int d = idx >> 5, rp = idx & 31;
        unsigned short h0 = __half_as_ushort(__float2half_rn(t[rp*2][d]));
        unsigned short h1 = __half_as_ushort(__float2half_rn(t[rp*2+1][d]));
        size_t o = ((size_t)head*64 + d)*SEQ + kc*64 + rp*2;
        *(unsigned*)(g_vt16 + o) = (unsigned)h0 | ((unsigned)h1 << 16);
    }
}

// -------- score GEMM (HMMA, split bf16) -> u16 bins (streaming stores) -------
__global__ __launch_bounds__(256) void k_score() {
    extern __shared__ __nv_bfloat16 sm[];
    const int TQH = 0, TQL = 128*STRD, TKH = 2*128*STRD, TKL = 3*128*STRD;
    int tid = threadIdx.x, wid = tid >> 5, lane = tid & 31;
    int kt = blockIdx.x, qt = blockIdx.y, head = blockIdx.z;

    size_t bq = ((size_t)head*SEQ + qt*128) * 64;
    size_t bk = ((size_t)head*SEQ + kt*128) * 64;
    const uint4* srcs[4] = { (const uint4*)(g_qhi+bq), (const uint4*)(g_qlo+bq),
                             (const uint4*)(g_khi+bk), (const uint4*)(g_klo+bk) };
    const int bases[4] = { TQH, TQL, TKH, TKL };
    #pragma unroll
    for (int a = 0; a < 4; a++)
        #pragma unroll
        for (int j = 0; j < 4; j++) {
            int idx = tid + j*256;
            int r = idx >> 3, c = idx & 7;
            uint4 v = srcs[a][idx];
            *(uint4*)&sm[bases[a] + r*STRD + c*8] = v;
        }
    __syncthreads();

    unsigned sb = s2u(sm);
    unsigned arow = wid*16 + (lane & 15);
    unsigned acol = (lane >> 4) * 8;
    unsigned aH = sb + (TQH + arow*STRD + acol) * 2;
    unsigned aL = sb + (TQL + arow*STRD + acol) * 2;
    unsigned ah[4][4], al[4][4];
    #pragma unroll
    for (int ks = 0; ks < 4; ks++) { ldm4(ah[ks], aH + ks*32); ldm4(al[ks], aL + ks*32); }

    unsigned brow = (lane & 7) + ((lane >> 4) << 3);
    unsigned bcol = ((lane >> 3) & 1) * 8;
    unsigned bH = sb + (TKH + brow*STRD + bcol) * 2;
    unsigned bL = sb + (TKL + brow*STRD + bcol) * 2;

    float acc[16][4];
    #pragma unroll
    for (int i = 0; i < 16; i++) { acc[i][0]=0; acc[i][1]=0; acc[i][2]=0; acc[i][3]=0; }

    #pragma unroll
    for (int np = 0; np < 8; np++) {
        #pragma unroll
        for (int ks = 0; ks < 4; ks++) {
            unsigned bh[4], bl[4];
            ldm4(bh, bH + np*16*STRD*2 + ks*32);
            ldm4(bl, bL + np*16*STRD*2 + ks*32);
            mma_bf16(acc[2*np],   ah[ks], bh[0], bh[1]);
            mma_bf16(acc[2*np+1], ah[ks], bh[2], bh[3]);
            mma_bf16(acc[2*np],   ah[ks], bl[0], bl[1]);
            mma_bf16(acc[2*np+1], ah[ks], bl[2], bl[3]);
            mma_bf16(acc[2*np],   al[ks], bh[0], bh[1]);
            mma_bf16(acc[2*np+1], al[ks], bh[2], bh[3]);
        }
    }

    int r0 = wid*16 + (lane >> 2);
    int cb = (lane & 3) * 2;
    unsigned short* bp0 = g_bins + ((size_t)head*SEQ + qt*128 + r0) * SEQ + kt*128;
    unsigned short* bp1 = bp0 + 8*SEQ;
    #pragma unroll
    for (int nt = 0; nt < 16; nt++) {
        int c = nt*8 + cb;
        unsigned b0 = binof(acc[nt][0]), b1 = binof(acc[nt][1]);
        unsigned b2 = binof(acc[nt][2]), b3 = binof(acc[nt][3]);
        __stcs((unsigned*)&bp0[c], b0 | (b1 << 16));
        __stcs((unsigned*)&bp1[c], b2 | (b3 << 16));
    }
}

// -- histogram: interleaved 8 replicas/bin (32B span), L2-resident counters ---
__global__ __launch_bounds__(256) void k_hist() {
    int tid = threadIdx.x;
    int lane = tid & 31;
    #pragma unroll
    for (int j = 0; j < 2; j++) {
        unsigned gi = blockIdx.x * 512u + j*256 + tid;       // uint4 index (8 bins)
        uint4 v = __ldcs((const uint4*)g_bins + gi);
        unsigned* h = g_hist2 + (((size_t)(gi >> 17)) << 17); // head * NB*8 words
        unsigned r0 = (lane*2 + j) & 7;
        atomicAdd(&h[((v.x & 0xffffu) << 3) + r0],          1u);
        atomicAdd(&h[((v.x >> 16)     << 3) + ((r0+1)&7)],  1u);
        atomicAdd(&h[((v.y & 0xffffu) << 3) + ((r0+2)&7)],  1u);
        atomicAdd(&h[((v.y >> 16)     << 3) + ((r0+3)&7)],  1u);
        atomicAdd(&h[((v.z & 0xffffu) << 3) + ((r0+4)&7)],  1u);
        atomicAdd(&h[((v.z >> 16)     << 3) + ((r0+5)&7)],  1u);
        atomicAdd(&h[((v.w & 0xffffu) << 3) + ((r0+6)&7)],  1u);
        atomicAdd(&h[((v.w >> 16)     << 3) + ((r0+7)&7)],  1u);
    }
}

// ---- reduce replicas -> per-bin counts + chunk sums; ZERO counters in place --
__global__ __launch_bounds__(256) void k_hpart() {
    int head = blockIdx.y, chunk = blockIdx.x, t = threadIdx.x;
    uint4* h = (uint4*)(g_hist2 + ((size_t)head << 17));     // bin -> 2 uint4
    unsigned* cnt = g_cnt + (size_t)head*NB;
    unsigned tot = 0;
    uint4 z = make_uint4(0u,0u,0u,0u);
    #pragma unroll
    for (int b = 0; b < 4; b++) {
        int bin = chunk*1024 + t + b*256;
        uint4 a0 = __ldcs((const uint4*)h + bin*2);
        uint4 a1 = __ldcs((const uint4*)h + bin*2 + 1);
        unsigned s = a0.x+a0.y+a0.z+a0.w + a1.x+a1.y+a1.z+a1.w;
        cnt[bin] = s;
        tot += s;
        h[bin*2] = z; h[bin*2 + 1] = z;        // reset for next replay
    }
    __shared__ unsigned sm[8];
    #pragma unroll
    for (int o = 16; o; o >>= 1) tot += __shfl_xor_sync(0xffffffffu, tot, o);
    if ((t & 31) == 0) sm[t >> 5] = tot;
    __syncthreads();
    if (t < 8) {
        unsigned v = sm[t];
        #pragma unroll
        for (int o = 4; o; o >>= 1) v += __shfl_xor_sync(0xffu, v, o);
        if (t == 0) g_part[head*16 + chunk] = v;
    }
}
__global__ __launch_bounds__(16) void k_hscan() {
    int head = blockIdx.x, t = threadIdx.x;
    unsigned v = g_part[head*16 + t];
    unsigned s = v;
    #pragma unroll
    for (int off = 1; off < 16; off <<= 1) {
        unsigned o = __shfl_down_sync(0xffffu, s, off);
        if (t + off < 16) s += o;
    }
    g_part[head*16 + t] = s - v;
}
__global__ __launch_bounds__(256) void k_hfinal() {
    int head = blockIdx.y, chunk = blockIdx.x, t = threadIdx.x;
    const unsigned* h = g_cnt + (size_t)head*NB + chunk*1024;
    uint4 v = ((const uint4*)h)[t];
    unsigned tot = v.x + v.y + v.z + v.w;
    __shared__ unsigned s[256];
    s[t] = tot; __syncthreads();
    for (int off = 1; off < 256; off <<= 1) {
        unsigned add = (t + off < 256) ? s[t + off] : 0u;
        __syncthreads();
        s[t] += add;
        __syncthreads();
    }
    unsigned above = s[t] - tot + g_part[head*16 + chunk];
    unsigned SA3 = above;
    unsigned SA2 = SA3 + v.w;
    unsigned SA1 = SA2 + v.z;
    unsigned SA0 = SA1 + v.y;
    float w0 = -__logf(((float)SA0 + 0.5f*((float)v.x - 1.0f) + 1.0f) * INV_N);
    float w1 = -__logf(((float)SA1 + 0.5f*((float)v.y - 1.0f) + 1.0f) * INV_N);
    float w2 = -__logf(((float)SA2 + 0.5f*((float)v.z - 1.0f) + 1.0f) * INV_N);
    float w3 = -__logf(((float)SA3 + 0.5f*((float)v.w - 1.0f) + 1.0f) * INV_N);
    unsigned p0 = (unsigned)__half_as_ushort(__float2half_rn(w0))
                | ((unsigned)__half_as_ushort(__float2half_rn(w1)) << 16);
    unsigned p1 = (unsigned)__half_as_ushort(__float2half_rn(w2))
                | ((unsigned)__half_as_ushort(__float2half_rn(w3)) << 16);
    ((uint2*)(g_wlut + (size_t)head*NB))[chunk*256 + t] = make_uint2(p0, p1);
}

// ---------------- output GEMM: bins -> (smem LUT) -> fp16 W, O=(W@V)/rowsum --
#define OS_LUT 0
#define OS_W   32768
#define OS_V   (32768 + 128*STRD*2)
#define OS_RS  (32768 + 128*STRD*2 + 64*STRD*2)
#define OS_TOT (OS_RS + 512)
__global__ __launch_bounds__(256, 2) void k_out(float* __restrict__ O) {
    extern __shared__ char smc[];
    unsigned short* lut = (unsigned short*)(smc + OS_LUT);
    unsigned short* Ws  = (unsigned short*)(smc + OS_W);
    unsigned short* Vs  = (unsigned short*)(smc + OS_V);
    float* rs           = (float*)(smc + OS_RS);
    int tid = threadIdx.x, wid = tid >> 5, lane = tid & 31;
    int qt = blockIdx.x, head = blockIdx.y;

    {
        const uint4* src = (const uint4*)(g_wlut + (size_t)head*NB);
        uint4* dst = (uint4*)lut;
        #pragma unroll
        for (int j = 0; j < 8; j++) dst[tid + j*256] = src[tid + j*256];
    }
    __syncthreads();

    size_t wbase = (size_t)head*SEQ + qt*128;
    size_t vbase = (size_t)head*64;

    unsigned sb = s2u(smc);
    unsigned arow = wid*16 + (lane & 15);
    unsigned acol = (lane >> 4) * 8;
    unsigned aA = sb + OS_W + (arow*STRD + acol) * 2;
    unsigned brow = (lane & 7) + ((lane >> 4) << 3);
    unsigned bcol = ((lane >> 3) & 1) * 8;
    unsigned bB = sb + OS_V + (brow*STRD + bcol) * 2;

    float acc[8][4];
    #pragma unroll
    for (int i = 0; i < 8; i++) { acc[i][0]=0; acc[i][1]=0; acc[i][2]=0; acc[i][3]=0; }
    float psum[4] = {0.f, 0.f, 0.f, 0.f};

    for (int ch = 0; ch < 16; ch++) {
        #pragma unroll
        for (int j = 0; j < 4; j++) {
            int idx = tid + j*256;
            int r = idx >> 3, c = idx & 7;
            uint4 b = __ldcs((const uint4*)(g_bins + (wbase + r)*SEQ + ch*64 + c*8));
            unsigned short w0 = lut[b.x & 0xffffu], w1 = lut[b.x >> 16];
            unsigned short w2 = lut[b.y & 0xffffu], w3 = lut[b.y >> 16];
            unsigned short w4 = lut[b.z & 0xffffu], w5 = lut[b.z >> 16];
            unsigned short w6 = lut[b.w & 0xffffu], w7 = lut[b.w >> 16];
            uint4 wv;
            wv.x = (unsigned)w0 | ((unsigned)w1 << 16);
            wv.y = (unsigned)w2 | ((unsigned)w3 << 16);
            wv.z = (unsigned)w4 | ((unsigned)w5 << 16);
            wv.w = (unsigned)w6 | ((unsigned)w7 << 16);
            *(uint4*)&Ws[r*STRD + c*8] = wv;
            psum[j] += __half2float(__ushort_as_half(w0)) + __half2float(__ushort_as_half(w1))
                     + __half2float(__ushort_as_half(w2)) + __half2float(__ushort_as_half(w3))
                     + __half2float(__ushort_as_half(w4)) + __half2float(__ushort_as_half(w5))
                     + __half2float(__ushort_as_half(w6)) + __half2float(__ushort_as_half(w7));
        }
        #pragma unroll
        for (int j = 0; j < 2; j++) {
            int idx = tid + j*256;
            int r = idx >> 3, c = idx & 7;
            *(uint4*)&Vs[r*STRD + c*8] =
                *(const uint4*)(g_vt16 + (vbase + r)*SEQ + ch*64 + c*8);
        }
        __syncthreads();

        unsigned af[4][4];
        #pragma unroll
        for (int ks = 0; ks < 4; ks++) ldm4(af[ks], aA + ks*32);
        #pragma unroll
        for (int np = 0; np < 4; np++) {
            #pragma unroll
            for (int ks = 0; ks < 4; ks++) {
                unsigned bf[4];
                ldm4(bf, bB + np*16*STRD*2 + ks*32);
                mma_f16(acc[2*np],   af[ks], bf[0], bf[1]);
                mma_f16(acc[2*np+1], af[ks], bf[2], bf[3]);
            }
        }
        __syncthreads();
    }

    #pragma unroll
    for (int j = 0; j < 4; j++) {
        float v = psum[j];
        v += __shfl_down_sync(0xffffffffu, v, 4);
        v += __shfl_down_sync(0xffffffffu, v, 2);
        v += __shfl_down_sync(0xffffffffu, v, 1);
        if ((tid & 7) == 0) rs[(tid >> 3) + 32*j] = v;
    }
    __syncthreads();

    int r0 = wid*16 + (lane >> 2);
    int cb = (lane & 3) * 2;
    float inv0 = 1.0f / rs[r0];
    float inv1 = 1.0f / rs[r0 + 8];
    float* op0 = O + ((size_t)head*SEQ + qt*128 + r0) * 64;
    float* op1 = op0 + 8*64;
    #pragma unroll
    for (int nt = 0; nt < 8; nt++) {
        int c = nt*8 + cb;
        *(float2*)&op0[c] = make_float2(acc[nt][0]*inv0, acc[nt][1]*inv0);
        *(float2*)&op1[c] = make_float2(acc[nt][2]*inv1, acc[nt][3]*inv1);
    }
}

// ---------------- launch (single stream, serial — measured fastest) ---------
extern "C" void kernel_launch(void* const* d_in, const int* in_sizes, int n_in,
                              void* d_out, int out_size) {
    const float* q = (const float*)d_in[0];
    const float* k = (const float*)d_in[1];
    const float* v = (const float*)d_in[2];
    float* o = (float*)d_out;

    cudaFuncSetAttribute(k_score, cudaFuncAttributeMaxDynamicSharedMemorySize, 4*128*STRD*2);
    cudaFuncSetAttribute(k_out,   cudaFuncAttributeMaxDynamicSharedMemorySize, OS_TOT);

    k_qksplit<<<16384, 256>>>(q, k);
    k_vsplit <<<dim3(16,64), 256>>>(v);
    k_score  <<<dim3(8,8,64), 256, 4*128*STRD*2>>>();
    k_hist   <<<16384, 256>>>();
    k_hpart  <<<dim3(16,64), 256>>>();
    k_hscan  <<<64, 16>>>();
    k_hfinal <<<dim3(16,64), 256>>>();
    k_out    <<<dim3(8,64), 256, OS_TOT>>>(o);
}

// round 16
// speedup vs baseline: 1.2751x; 1.1239x over previous
#include <cuda_runtime.h>
#include <cuda_bf16.h>
#include <cuda_fp16.h>

#define SEQ   1024
#define DIM   64
#define BH    64
#define NB    16384
#define INV_N (1.0f/1048576.0f)
#define STRD  72          // smem row stride in 16-bit units (144B) -> conflict-free ldmatrix

// ---------------- scratch ----------------
__device__ __nv_bfloat16 g_qhi[(size_t)BH*SEQ*DIM];
__device__ __nv_bfloat16 g_qlo[(size_t)BH*SEQ*DIM];
__device__ __nv_bfloat16 g_khi[(size_t)BH*SEQ*DIM];
__device__ __nv_bfloat16 g_klo[(size_t)BH*SEQ*DIM];
__device__ unsigned short g_vt16[(size_t)BH*DIM*SEQ];  // V^T fp16 [head][d][k] (8MB)
__device__ unsigned short g_bins[(size_t)BH*SEQ*SEQ];  // u16 bin per score (128MB)
__device__ unsigned      g_hist2[(size_t)BH*NB*8];     // 8 u32 interleaved replicas/bin (32MB)
__device__ unsigned      g_cnt[(size_t)BH*NB];         // per-bin totals (4MB)
__device__ unsigned short g_wlut[(size_t)BH*NB];       // fp16 weight per bin (2MB)
__device__ unsigned      g_part[BH*16];

// ---------------- helpers ----------------
__device__ __forceinline__ int binof(float x) {
    int b = (int)((x + 1.0f) * 8192.0f);
    b = b < 0 ? 0 : b;
    b = b > (NB-1) ? (NB-1) : b;
    return b;
}
__device__ __forceinline__ unsigned s2u(const void* p) {
    unsigned a;
    asm("{ .reg .u64 t; cvta.to.shared.u64 t, %1; cvt.u32.u64 %0, t; }" : "=r"(a) : "l"(p));
    return a;
}
__device__ __forceinline__ void ldm4(unsigned r[4], unsigned a) {
    asm volatile("ldmatrix.sync.aligned.m8n8.x4.shared.b16 {%0,%1,%2,%3}, [%4];"
        : "=r"(r[0]), "=r"(r[1]), "=r"(r[2]), "=r"(r[3]) : "r"(a));
}
__device__ __forceinline__ void mma_bf16(float c[4], const unsigned a[4],
                                         unsigned b0, unsigned b1) {
    asm volatile("mma.sync.aligned.m16n8k16.row.col.f32.bf16.bf16.f32 "
        "{%0,%1,%2,%3}, {%4,%5,%6,%7}, {%8,%9}, {%0,%1,%2,%3};"
        : "+f"(c[0]), "+f"(c[1]), "+f"(c[2]), "+f"(c[3])
        : "r"(a[0]), "r"(a[1]), "r"(a[2]), "r"(a[3]), "r"(b0), "r"(b1));
}
__device__ __forceinline__ void mma_f16(float c[4], const unsigned a[4],
                                        unsigned b0, unsigned b1) {
    asm volatile("mma.sync.aligned.m16n8k16.row.col.f32.f16.f16.f32 "
        "{%0,%1,%2,%3}, {%4,%5,%6,%7}, {%8,%9}, {%0,%1,%2,%3};"
        : "+f"(c[0]), "+f"(c[1]), "+f"(c[2]), "+f"(c[3])
        : "r"(a[0]), "r"(a[1]), "r"(a[2]), "r"(a[3]), "r"(b0), "r"(b1));
}
__device__ __forceinline__ void split2(float x, __nv_bfloat16& h, __nv_bfloat16& l) {
    h = __float2bfloat16_rn(x);
    l = __float2bfloat16_rn(x - __bfloat162float(h));
}

// ---------------- normalize + split Q,K to bf16 hi/lo ----------------
__global__ __launch_bounds__(256) void k_qksplit(const float* __restrict__ q,
                                                 const float* __restrict__ k) {
    int w    = blockIdx.x * 8 + (threadIdx.x >> 5);
    int lane = threadIdx.x & 31;
    int r    = w & 65535;
    const float* src = (w < 65536) ? q + (size_t)r*64 : k + (size_t)r*64;
    __nv_bfloat16* dh = (w < 65536) ? g_qhi : g_khi;
    __nv_bfloat16* dl = (w < 65536) ? g_qlo : g_klo;
    float x0 = src[lane], x1 = src[lane+32];
    float ss = x0*x0 + x1*x1;
    #pragma unroll
    for (int o = 16; o; o >>= 1) ss += __shfl_xor_sync(0xffffffffu, ss, o);
    float inv = 1.0f / (sqrtf(ss) + 1e-5f);
    x0 *= inv; x1 *= inv;
    __nv_bfloat16 h, l;
    split2(x0, h, l); dh[(size_t)r*64 + lane]      = h; dl[(size_t)r*64 + lane]      = l;
    split2(x1, h, l); dh[(size_t)r*64 + lane + 32] = h; dl[(size_t)r*64 + lane + 32] = l;
}

// ---------------- transpose V -> fp16 V^T ----------------
__global__ __launch_bounds__(256) void k_vsplit(const float* __restrict__ V) {
    __shared__ float t[64][65];
    int head = blockIdx.y, kc = blockIdx.x, tid = threadIdx.x;
    const float* src = V + ((size_t)head*SEQ + kc*64) * 64;
    #pragma unroll
    for (int i = 0; i < 4; i++) {
        int idx = tid + i*256;
        int r = idx >> 4, c4 = idx & 15;
        float4 v = ((const float4*)(src + (size_t)r*64))[c4];
        t[r][c4*4+0]=v.x; t[r][c4*4+1]=v.y; t[r][c4*4+2]=v.z; t[r][c4*4+3]=v.w;
    }
    __syncthreads();
    #pragma unroll
    for (int i = 0; i < 8; i++) {
        int idx = tid + i*256;
        int d = idx >> 5, rp = idx & 31;
        unsigned short h0 = __half_as_ushort(__float2half_rn(t[rp*2][d]));
        unsigned short h1 = __half_as_ushort(__float2half_rn(t[rp*2+1][d]));
        size_t o = ((size_t)head*64 + d)*SEQ + kc*64 + rp*2;
        *(unsigned*)(g_vt16 + o) = (unsigned)h0 | ((unsigned)h1 << 16);
    }
}

// -- score GEMM (HMMA, split bf16) -> u16 bins + FUSED replica atomics --------
// REDG is fire-and-forget (no return latency); with 2 CTAs/SM the GEMM work
// interleaves with atomic issue. __launch_bounds__(256,2) pins regs <= 128.
__global__ __launch_bounds__(256, 2) void k_score() {
    extern __shared__ __nv_bfloat16 sm[];
    const int TQH = 0, TQL = 128*STRD, TKH = 2*128*STRD, TKL = 3*128*STRD;
    int tid = threadIdx.x, wid = tid >> 5, lane = tid & 31;
    int kt = blockIdx.x, qt = blockIdx.y, head = blockIdx.z;

    size_t bq = ((size_t)head*SEQ + qt*128) * 64;
    size_t bk = ((size_t)head*SEQ + kt*128) * 64;
    const uint4* srcs[4] = { (const uint4*)(g_qhi+bq), (const uint4*)(g_qlo+bq),
                             (const uint4*)(g_khi+bk), (const uint4*)(g_klo+bk) };
    const int bases[4] = { TQH, TQL, TKH, TKL };
    #pragma unroll
    for (int a = 0; a < 4; a++)
        #pragma unroll
        for (int j = 0; j < 4; j++) {
            int idx = tid + j*256;
            int r = idx >> 3, c = idx & 7;
            uint4 v = srcs[a][idx];
            *(uint4*)&sm[bases[a] + r*STRD + c*8] = v;
        }
    __syncthreads();

    unsigned sb = s2u(sm);
    unsigned arow = wid*16 + (lane & 15);
    unsigned acol = (lane >> 4) * 8;
    unsigned aH = sb + (TQH + arow*STRD + acol) * 2;
    unsigned aL = sb + (TQL + arow*STRD + acol) * 2;
    unsigned ah[4][4], al[4][4];
    #pragma unroll
    for (int ks = 0; ks < 4; ks++) { ldm4(ah[ks], aH + ks*32); ldm4(al[ks], aL + ks*32); }

    unsigned brow = (lane & 7) + ((lane >> 4) << 3);
    unsigned bcol = ((lane >> 3) & 1) * 8;
    unsigned bH = sb + (TKH + brow*STRD + bcol) * 2;
    unsigned bL = sb + (TKL + brow*STRD + bcol) * 2;

    float acc[16][4];
    #pragma unroll
    for (int i = 0; i < 16; i++) { acc[i][0]=0; acc[i][1]=0; acc[i][2]=0; acc[i][3]=0; }

    #pragma unroll
    for (int np = 0; np < 8; np++) {
        #pragma unroll
        for (int ks = 0; ks < 4; ks++) {
            unsigned bh[4], bl[4];
            ldm4(bh, bH + np*16*STRD*2 + ks*32);
            ldm4(bl, bL + np*16*STRD*2 + ks*32);
            mma_bf16(acc[2*np],   ah[ks], bh[0], bh[1]);
            mma_bf16(acc[2*np+1], ah[ks], bh[2], bh[3]);
            mma_bf16(acc[2*np],   ah[ks], bl[0], bl[1]);
            mma_bf16(acc[2*np+1], ah[ks], bl[2], bl[3]);
            mma_bf16(acc[2*np],   al[ks], bh[0], bh[1]);
            mma_bf16(acc[2*np+1], al[ks], bh[2], bh[3]);
        }
    }

    int r0r = wid*16 + (lane >> 2);
    int cb = (lane & 3) * 2;
    unsigned short* bp0 = g_bins + ((size_t)head*SEQ + qt*128 + r0r) * SEQ + kt*128;
    unsigned short* bp1 = bp0 + 8*SEQ;
    unsigned* h = g_hist2 + ((size_t)head << 17);   // NB*8 words per head
    #pragma unroll
    for (int nt = 0; nt < 16; nt++) {
        int c = nt*8 + cb;
        unsigned b0 = binof(acc[nt][0]), b1 = binof(acc[nt][1]);
        unsigned b2 = binof(acc[nt][2]), b3 = binof(acc[nt][3]);
        __stcs((unsigned*)&bp0[c], b0 | (b1 << 16));
        __stcs((unsigned*)&bp1[c], b2 | (b3 << 16));
        unsigned r0 = (lane + nt) & 7;
        atomicAdd(&h[(b0 << 3) + r0],          1u);
        atomicAdd(&h[(b1 << 3) + ((r0+2)&7)],  1u);
        atomicAdd(&h[(b2 << 3) + ((r0+4)&7)],  1u);
        atomicAdd(&h[(b3 << 3) + ((r0+6)&7)],  1u);
    }
}

// ---- reduce replicas -> per-bin counts + chunk sums; ZERO counters in place --
__global__ __launch_bounds__(256) void k_hpart() {
    int head = blockIdx.y, chunk = blockIdx.x, t = threadIdx.x;
    uint4* h = (uint4*)(g_hist2 + ((size_t)head << 17));     // bin -> 2 uint4
    unsigned* cnt = g_cnt + (size_t)head*NB;
    unsigned tot = 0;
    uint4 z = make_uint4(0u,0u,0u,0u);
    #pragma unroll
    for (int b = 0; b < 4; b++) {
        int bin = chunk*1024 + t + b*256;
        uint4 a0 = __ldcs((const uint4*)h + bin*2);
        uint4 a1 = __ldcs((const uint4*)h + bin*2 + 1);
        unsigned s = a0.x+a0.y+a0.z+a0.w + a1.x+a1.y+a1.z+a1.w;
        cnt[bin] = s;
        tot += s;
        h[bin*2] = z; h[bin*2 + 1] = z;        // reset for next replay
    }
    __shared__ unsigned sm[8];
    #pragma unroll
    for (int o = 16; o; o >>= 1) tot += __shfl_xor_sync(0xffffffffu, tot, o);
    if ((t & 31) == 0) sm[t >> 5] = tot;
    __syncthreads();
    if (t < 8) {
        unsigned v = sm[t];
        #pragma unroll
        for (int o = 4; o; o >>= 1) v += __shfl_xor_sync(0xffu, v, o);
        if (t == 0) g_part[head*16 + chunk] = v;
    }
}
__global__ __launch_bounds__(16) void k_hscan() {
    int head = blockIdx.x, t = threadIdx.x;
    unsigned v = g_part[head*16 + t];
    unsigned s = v;
    #pragma unroll
    for (int off = 1; off < 16; off <<= 1) {
        unsigned o = __shfl_down_sync(0xffffu, s, off);
        if (t + off < 16) s += o;
    }
    g_part[head*16 + t] = s - v;
}
__global__ __launch_bounds__(256) void k_hfinal() {
    int head = blockIdx.y, chunk = blockIdx.x, t = threadIdx.x;
    const unsigned* h = g_cnt + (size_t)head*NB + chunk*1024;
    uint4 v = ((const uint4*)h)[t];
    unsigned tot = v.x + v.y + v.z + v.w;
    __shared__ unsigned s[256];
    s[t] = tot; __syncthreads();
    for (int off = 1; off < 256; off <<= 1) {
        unsigned add = (t + off < 256) ? s[t + off] : 0u;
        __syncthreads();
        s[t] += add;
        __syncthreads();
    }
    unsigned above = s[t] - tot + g_part[head*16 + chunk];
    unsigned SA3 = above;
    unsigned SA2 = SA3 + v.w;
    unsigned SA1 = SA2 + v.z;
    unsigned SA0 = SA1 + v.y;
    float w0 = -__logf(((float)SA0 + 0.5f*((float)v.x - 1.0f) + 1.0f) * INV_N);
    float w1 = -__logf(((float)SA1 + 0.5f*((float)v.y - 1.0f) + 1.0f) * INV_N);
    float w2 = -__logf(((float)SA2 + 0.5f*((float)v.z - 1.0f) + 1.0f) * INV_N);
    float w3 = -__logf(((float)SA3 + 0.5f*((float)v.w - 1.0f) + 1.0f) * INV_N);
    unsigned p0 = (unsigned)__half_as_ushort(__float2half_rn(w0))
                | ((unsigned)__half_as_ushort(__float2half_rn(w1)) << 16);
    unsigned p1 = (unsigned)__half_as_ushort(__float2half_rn(w2))
                | ((unsigned)__half_as_ushort(__float2half_rn(w3)) << 16);
    ((uint2*)(g_wlut + (size_t)head*NB))[chunk*256 + t] = make_uint2(p0, p1);
}

// ---------------- output GEMM: bins -> (smem LUT) -> fp16 W, O=(W@V)/rowsum --
#define OS_LUT 0
#define OS_W   32768
#define OS_V   (32768 + 128*STRD*2)
#define OS_RS  (32768 + 128*STRD*2 + 64*STRD*2)
#define OS_TOT (OS_RS + 512)
__global__ __launch_bounds__(256, 2) void k_out(float* __restrict__ O) {
    extern __shared__ char smc[];
    unsigned short* lut = (unsigned short*)(smc + OS_LUT);
    unsigned short* Ws  = (unsigned short*)(smc + OS_W);
    unsigned short* Vs  = (unsigned short*)(smc + OS_V);
    float* rs           = (float*)(smc + OS_RS);
    int tid = threadIdx.x, wid = tid >> 5, lane = tid & 31;
    int qt = blockIdx.x, head = blockIdx.y;

    {
        const uint4* src = (const uint4*)(g_wlut + (size_t)head*NB);
        uint4* dst = (uint4*)lut;
        #pragma unroll
        for (int j = 0; j < 8; j++) dst[tid + j*256] = src[tid + j*256];
    }
    __syncthreads();

    size_t wbase = (size_t)head*SEQ + qt*128;
    size_t vbase = (size_t)head*64;

    unsigned sb = s2u(smc);
    unsigned arow = wid*16 + (lane & 15);
    unsigned acol = (lane >> 4) * 8;
    unsigned aA = sb + OS_W + (arow*STRD + acol) * 2;
    unsigned brow = (lane & 7) + ((lane >> 4) << 3);
    unsigned bcol = ((lane >> 3) & 1) * 8;
    unsigned bB = sb + OS_V + (brow*STRD + bcol) * 2;

    float acc[8][4];
    #pragma unroll
    for (int i = 0; i < 8; i++) { acc[i][0]=0; acc[i][1]=0; acc[i][2]=0; acc[i][3]=0; }
    float psum[4] = {0.f, 0.f, 0.f, 0.f};

    for (int ch = 0; ch < 16; ch++) {
        #pragma unroll
        for (int j = 0; j < 4; j++) {
            int idx = tid + j*256;
            int r = idx >> 3, c = idx & 7;
            uint4 b = __ldcs((const uint4*)(g_bins + (wbase + r)*SEQ + ch*64 + c*8));
            unsigned short w0 = lut[b.x & 0xffffu], w1 = lut[b.x >> 16];
            unsigned short w2 = lut[b.y & 0xffffu], w3 = lut[b.y >> 16];
            unsigned short w4 = lut[b.z & 0xffffu], w5 = lut[b.z >> 16];
            unsigned short w6 = lut[b.w & 0xffffu], w7 = lut[b.w >> 16];
            uint4 wv;
            wv.x = (unsigned)w0 | ((unsigned)w1 << 16);
            wv.y = (unsigned)w2 | ((unsigned)w3 << 16);
            wv.z = (unsigned)w4 | ((unsigned)w5 << 16);
            wv.w = (unsigned)w6 | ((unsigned)w7 << 16);
            *(uint4*)&Ws[r*STRD + c*8] = wv;
            psum[j] += __half2float(__ushort_as_half(w0)) + __half2float(__ushort_as_half(w1))
                     + __half2float(__ushort_as_half(w2)) + __half2float(__ushort_as_half(w3))
                     + __half2float(__ushort_as_half(w4)) + __half2float(__ushort_as_half(w5))
                     + __half2float(__ushort_as_half(w6)) + __half2float(__ushort_as_half(w7));
        }
        #pragma unroll
        for (int j = 0; j < 2; j++) {
            int idx = tid + j*256;
            int r = idx >> 3, c = idx & 7;
            *(uint4*)&Vs[r*STRD + c*8] =
                *(const uint4*)(g_vt16 + (vbase + r)*SEQ + ch*64 + c*8);
        }
        __syncthreads();

        unsigned af[4][4];
        #pragma unroll
        for (int ks = 0; ks < 4; ks++) ldm4(af[ks], aA + ks*32);
        #pragma unroll
        for (int np = 0; np < 4; np++) {
            #pragma unroll
            for (int ks = 0; ks < 4; ks++) {
                unsigned bf[4];
                ldm4(bf, bB + np*16*STRD*2 + ks*32);
                mma_f16(acc[2*np],   af[ks], bf[0], bf[1]);
                mma_f16(acc[2*np+1], af[ks], bf[2], bf[3]);
            }
        }
        __syncthreads();
    }

    #pragma unroll
    for (int j = 0; j < 4; j++) {
        float v = psum[j];
        v += __shfl_down_sync(0xffffffffu, v, 4);
        v += __shfl_down_sync(0xffffffffu, v, 2);
        v += __shfl_down_sync(0xffffffffu, v, 1);
        if ((tid & 7) == 0) rs[(tid >> 3) + 32*j] = v;
    }
    __syncthreads();

    int r0 = wid*16 + (lane >> 2);
    int cb = (lane & 3) * 2;
    float inv0 = 1.0f / rs[r0];
    float inv1 = 1.0f / rs[r0 + 8];
    float* op0 = O + ((size_t)head*SEQ + qt*128 + r0) * 64;
    float* op1 = op0 + 8*64;
    #pragma unroll
    for (int nt = 0; nt < 8; nt++) {
        int c = nt*8 + cb;
        *(float2*)&op0[c] = make_float2(acc[nt][0]*inv0, acc[nt][1]*inv0);
        *(float2*)&op1[c] = make_float2(acc[nt][2]*inv1, acc[nt][3]*inv1);
    }
}

// ---------------- launch (single stream, serial) ----------------
extern "C" void kernel_launch(void* const* d_in, const int* in_sizes, int n_in,
                              void* d_out, int out_size) {
    const float* q = (const float*)d_in[0];
    const float* k = (const float*)d_in[1];
    const float* v = (const float*)d_in[2];
    float* o = (float*)d_out;

    cudaFuncSetAttribute(k_score, cudaFuncAttributeMaxDynamicSharedMemorySize, 4*128*STRD*2);
    cudaFuncSetAttribute(k_out,   cudaFuncAttributeMaxDynamicSharedMemorySize, OS_TOT);

    k_qksplit<<<16384, 256>>>(q, k);
    k_vsplit <<<dim3(16,64), 256>>>(v);
    k_score  <<<dim3(8,8,64), 256, 4*128*STRD*2>>>();
    k_hpart  <<<dim3(16,64), 256>>>();
    k_hscan  <<<64, 16>>>();
    k_hfinal <<<dim3(16,64), 256>>>();
    k_out    <<<dim3(8,64), 256, OS_TOT>>>(o);
}